// round 6
// baseline (speedup 1.0000x reference)
#include <cuda_runtime.h>
#include <cstdint>
#include <cstddef>

#define N_SP 4096
#define HB 4
#define LOG2E 1.4426950408889634f

typedef unsigned long long ull;

// ---------------- packed f32x2 helpers ----------------
__device__ __forceinline__ void ffma2(ull &d, ull a, ull b){
    asm("fma.rn.f32x2 %0, %1, %2, %0;" : "+l"(d) : "l"(a), "l"(b));
}
__device__ __forceinline__ void unpack2(ull v, float &lo, float &hi){
    asm("mov.b64 {%0, %1}, %2;" : "=f"(lo), "=f"(hi) : "l"(v));
}
__device__ __forceinline__ ull dup2(float x){
    ull r; asm("mov.b64 %0, {%1, %1};" : "=l"(r) : "f"(x)); return r;
}
__device__ __forceinline__ float fexp2(float x){
    float y; asm("ex2.approx.f32 %0, %1;" : "=f"(y) : "f"(x)); return y;
}

// ---------------- scratch (device globals; allocation is forbidden) ----------------
__device__ __align__(128) float g_x2u[HB*256*N_SP];
__device__ __align__(128) float g_x1u[HB*512*N_SP];
__device__ __align__(128) float g_q[HB*(64+32+16)*N_SP];
__device__ __align__(128) float g_k[HB*(64+32+16)*N_SP];
__device__ __align__(128) float g_s[3*HB*N_SP];
__device__ __align__(128) float g_a[3*HB*N_SP];
__device__ __align__(128) float g_u[3*512];
__device__ __align__(128) float g_sb[3];

#define Q_OFF0 0
#define Q_OFF1 (HB*64*N_SP)
#define Q_OFF2 (HB*(64+32)*N_SP)

// ---------------- bilinear upsample (align_corners=True) to 64x64 ----------------
__global__ void upsample_kernel(const float* __restrict__ in, float* __restrict__ out,
                                int planes, int isz)
{
    int idx = blockIdx.x * 256 + threadIdx.x;
    if (idx >= planes * N_SP) return;
    int ox = idx & 63, oy = (idx >> 6) & 63, p = idx >> 12;
    float r = (float)(isz - 1) / 63.0f;
    float cy = oy * r, cx = ox * r;
    int iy = (int)cy; if (iy > isz - 2) iy = isz - 2;
    int ix = (int)cx; if (ix > isz - 2) ix = isz - 2;
    float wy = cy - (float)iy, wx = cx - (float)ix;
    const float* base = in + (size_t)p * isz * isz;
    float v00 = base[iy*isz + ix],     v01 = base[iy*isz + ix + 1];
    float v10 = base[(iy+1)*isz + ix], v11 = base[(iy+1)*isz + ix + 1];
    float top = v00 + wx * (v01 - v00);
    float bot = v10 + wx * (v11 - v10);
    out[idx] = top + wy * (bot - top);
}

// ---------------- u = wa @ Wv (fold value path to 1 channel), sb = wa . bv ----------------
__global__ void u_kernel(const float* __restrict__ wa, const float* __restrict__ Wv,
                         const float* __restrict__ bv, float* __restrict__ u,
                         float* __restrict__ sb, int C)
{
    int c2 = blockIdx.x * 256 + threadIdx.x;
    if (c2 < C){
        float acc = 0.f;
        for (int c = 0; c < C; c++) acc += wa[c] * Wv[c*C + c2];
        u[c2] = acc;
    }
    if (blockIdx.x == 0 && threadIdx.x == 0){
        float acc = 0.f;
        for (int c = 0; c < C; c++) acc += wa[c] * bv[c];
        *sb = acc;
    }
}

// ---------------- s[b,m] = u . x[:,m] + sb ----------------
template<int C>
__global__ void s_kernel(const float* __restrict__ X, const float* __restrict__ u,
                         const float* __restrict__ sb, float* __restrict__ sout)
{
    int b = blockIdx.y;
    int n = blockIdx.x * 256 + threadIdx.x;
    const float* Xb = X + (size_t)b * C * N_SP + n;
    float acc = 0.f;
    #pragma unroll 8
    for (int c = 0; c < C; c++) acc += __ldg(&u[c]) * Xb[(size_t)c * N_SP];
    sout[b*N_SP + n] = acc + sb[0];
}

// ---------------- q/k projection (f32x2 tiled GEMM); q pre-scaled by log2e ----------------
// Out rows: 0..D-1 = q rows, D..2D-1 = k rows. Tile: 2D rows x 64 cols per block.
template<int C, int D>
__global__ __launch_bounds__(256) void qkprep_kernel(
    const float* __restrict__ X,
    const float* __restrict__ Wq, const float* __restrict__ bq,
    const float* __restrict__ Wk, const float* __restrict__ bk,
    float* __restrict__ qg, float* __restrict__ kg)
{
    constexpr int ROWS = 2*D;
    constexpr int RP = ROWS/32;            // row-pairs per thread
    __shared__ __align__(16) float Xs2[16*128]; // x duplicated in pairs, [cc][2n]
    __shared__ __align__(16) float Ws[16*ROWS]; // [cc][row]
    int tid = threadIdx.x;
    int cg = tid & 15, rg = tid >> 4;
    int b = blockIdx.y;
    int n0 = blockIdx.x * 64;
    const float* Xb = X + (size_t)b * C * N_SP;

    ull acc[RP][4];
    #pragma unroll
    for (int p = 0; p < RP; p++)
        #pragma unroll
        for (int j = 0; j < 4; j++) acc[p][j] = 0ull;

    for (int c0 = 0; c0 < C; c0 += 16){
        __syncthreads();
        #pragma unroll
        for (int i = 0; i < 4; i++){
            int idx = tid + i*256;
            int cc = idx >> 6, n = idx & 63;
            float v = Xb[(size_t)(c0+cc)*N_SP + n0 + n];
            *(float2*)&Xs2[cc*128 + 2*n] = make_float2(v, v);
        }
        #pragma unroll
        for (int i = 0; i < ROWS/16; i++){
            int idx = tid + i*256;
            int cc = idx & 15, r = idx >> 4;
            Ws[cc*ROWS + r] = (r < D) ? Wq[r*C + c0 + cc] : Wk[(r-D)*C + c0 + cc];
        }
        __syncthreads();
        #pragma unroll
        for (int cc = 0; cc < 16; cc++){
            const ulonglong2* xp = (const ulonglong2*)(Xs2 + cc*128 + cg*8);
            ulonglong2 xa = xp[0], xb2 = xp[1];
            ull x0 = xa.x, x1 = xa.y, x2 = xb2.x, x3 = xb2.y;
            #pragma unroll
            for (int p = 0; p < RP; p++){
                ull wpair = *(const ull*)&Ws[cc*ROWS + (rg*RP + p)*2];
                ffma2(acc[p][0], wpair, x0);
                ffma2(acc[p][1], wpair, x1);
                ffma2(acc[p][2], wpair, x2);
                ffma2(acc[p][3], wpair, x3);
            }
        }
    }
    #pragma unroll
    for (int p = 0; p < RP; p++){
        int r0 = (rg*RP + p)*2;
        #pragma unroll
        for (int j = 0; j < 4; j++){
            float lo, hi; unpack2(acc[p][j], lo, hi);
            int n = n0 + cg*4 + j;
            if (r0 < D){
                qg[((size_t)b*D + r0)*N_SP + n]     = (lo + bq[r0])   * LOG2E;
                qg[((size_t)b*D + r0 + 1)*N_SP + n] = (hi + bq[r0+1]) * LOG2E;
            } else {
                int rr = r0 - D;
                kg[((size_t)b*D + rr)*N_SP + n]     = lo + bk[rr];
                kg[((size_t)b*D + rr + 1)*N_SP + n] = hi + bk[rr+1];
            }
        }
    }
}

// ---------------- streaming attention with scalar values ----------------
// a[n] = ba + sum_m 2^(l[n,m]-M) s[m] / sum_m 2^(l[n,m]-M),   l = log2e*(q.k)
// Block: 64 rows. Warp w owns m-range [w*16, w*16+16) per 128-m tile; lane owns rows 2*lane, 2*lane+1.
template<int D>
__global__ __launch_bounds__(256, 2) void attn_kernel(
    const float* __restrict__ qg, const float* __restrict__ kg,
    const float* __restrict__ sg, const float* __restrict__ bap,
    float* __restrict__ aout)
{
    extern __shared__ float sm[];
    float* smq = sm;                  // D*128 floats (q duplicated in pairs)
    float* smk = sm + D*128;          // D*128 floats
    float* sms = smk + D*128;         // 128 floats
    float* smr = sms + 128;           // 8*64*4 floats
    int tid = threadIdx.x;
    int lane = tid & 31, w = tid >> 5;
    int b = blockIdx.y, n0 = blockIdx.x * 64;
    const float* qb = qg + (size_t)b * D * N_SP;
    const float* kb = kg + (size_t)b * D * N_SP;
    const float* sb = sg + (size_t)b * N_SP;

    #pragma unroll
    for (int i = 0; i < (D*64)/256; i++){
        int idx = tid + i*256;
        int kk = idx >> 6, n = idx & 63;
        float v = qb[(size_t)kk*N_SP + n0 + n];
        *(float2*)&smq[kk*128 + 2*n] = make_float2(v, v);
    }

    float mx0 = -1e30f, mx1 = -1e30f;
    float den0 = 0.f, den1 = 0.f, num0 = 0.f, num1 = 0.f;

    for (int mt = 0; mt < 32; mt++){
        __syncthreads();
        #pragma unroll
        for (int i = 0; i < (D*128)/1024; i++){
            int qi = tid + i*256;
            int kk = qi >> 5, mq = qi & 31;
            *(float4*)&smk[kk*128 + mq*4] =
                *(const float4*)&kb[(size_t)kk*N_SP + mt*128 + mq*4];
        }
        if (tid < 32)
            *(float4*)&sms[tid*4] = *(const float4*)&sb[mt*128 + tid*4];
        __syncthreads();

        ull acc[16];
        #pragma unroll
        for (int j = 0; j < 16; j++) acc[j] = 0ull;

        #pragma unroll 8
        for (int kk = 0; kk < D; kk++){
            ulonglong2 qp = ((const ulonglong2*)(smq + kk*128))[lane];
            const ulonglong2* kr = (const ulonglong2*)(smk + kk*128) + w*4;
            ulonglong2 k0 = kr[0], k1 = kr[1], k2 = kr[2], k3 = kr[3];
            ffma2(acc[0],  qp.x, k0.x); ffma2(acc[1],  qp.x, k0.y);
            ffma2(acc[2],  qp.x, k1.x); ffma2(acc[3],  qp.x, k1.y);
            ffma2(acc[4],  qp.x, k2.x); ffma2(acc[5],  qp.x, k2.y);
            ffma2(acc[6],  qp.x, k3.x); ffma2(acc[7],  qp.x, k3.y);
            ffma2(acc[8],  qp.y, k0.x); ffma2(acc[9],  qp.y, k0.y);
            ffma2(acc[10], qp.y, k1.x); ffma2(acc[11], qp.y, k1.y);
            ffma2(acc[12], qp.y, k2.x); ffma2(acc[13], qp.y, k2.y);
            ffma2(acc[14], qp.y, k3.x); ffma2(acc[15], qp.y, k3.y);
        }

        float sv[16];
        #pragma unroll
        for (int j = 0; j < 4; j++)
            *(float4*)&sv[4*j] = *(const float4*)&sms[w*16 + 4*j];

        {   // row 0 (n = n0 + 2*lane)
            float l[16];
            #pragma unroll
            for (int j = 0; j < 8; j++) unpack2(acc[j], l[2*j], l[2*j+1]);
            float tm = mx0;
            #pragma unroll
            for (int j = 0; j < 16; j++) tm = fmaxf(tm, l[j]);
            float sc = fexp2(mx0 - tm);
            den0 *= sc; num0 *= sc; mx0 = tm;
            float dl = 0.f, nl = 0.f;
            #pragma unroll
            for (int j = 0; j < 16; j++){
                float e = fexp2(l[j] - tm);
                dl += e; nl += e * sv[j];
            }
            den0 += dl; num0 += nl;
        }
        {   // row 1 (n = n0 + 2*lane + 1)
            float l[16];
            #pragma unroll
            for (int j = 0; j < 8; j++) unpack2(acc[8+j], l[2*j], l[2*j+1]);
            float tm = mx1;
            #pragma unroll
            for (int j = 0; j < 16; j++) tm = fmaxf(tm, l[j]);
            float sc = fexp2(mx1 - tm);
            den1 *= sc; num1 *= sc; mx1 = tm;
            float dl = 0.f, nl = 0.f;
            #pragma unroll
            for (int j = 0; j < 16; j++){
                float e = fexp2(l[j] - tm);
                dl += e; nl += e * sv[j];
            }
            den1 += dl; num1 += nl;
        }
    }

    // per-warp partials -> smem, reduce across the 8 warps
    {
        int r0 = lane*2;
        float* p0 = &smr[(w*64 + r0)*4];
        p0[0] = mx0; p0[1] = den0; p0[2] = num0;
        float* p1 = &smr[(w*64 + r0 + 1)*4];
        p1[0] = mx1; p1[1] = den1; p1[2] = num1;
    }
    __syncthreads();
    if (tid < 64){
        float M = -1e30f;
        #pragma unroll
        for (int i = 0; i < 8; i++) M = fmaxf(M, smr[(i*64 + tid)*4]);
        float dsum = 0.f, nsum = 0.f;
        #pragma unroll
        for (int i = 0; i < 8; i++){
            float e = fexp2(smr[(i*64 + tid)*4] - M);
            dsum += smr[(i*64 + tid)*4 + 1] * e;
            nsum += smr[(i*64 + tid)*4 + 2] * e;
        }
        aout[(size_t)b*N_SP + n0 + tid] = bap[0] + nsum / dsum;
    }
}

// ---------------- final fused conv: out = w2 . relu(prod * (W1 . xcat) + b1) + b2 ----------------
__global__ __launch_bounds__(128) void final_kernel(
    const float* __restrict__ x3, const float* __restrict__ w1,
    const float* __restrict__ b1, const float* __restrict__ w2,
    const float* __restrict__ b2, float* __restrict__ out)
{
    __shared__ __align__(16) float Ws2[32*32];
    int tid = threadIdx.x;
    int p = blockIdx.x * 128 + tid;
    int b = p >> 12, n = p & 4095;

    ull tacc[16];
    #pragma unroll
    for (int j = 0; j < 16; j++) tacc[j] = 0ull;

    for (int c0 = 0; c0 < 896; c0 += 32){
        __syncthreads();
        #pragma unroll
        for (int i = 0; i < 8; i++){
            int idx = tid + i*128;
            int o = idx >> 5, cc = idx & 31;
            Ws2[cc*32 + o] = w1[o*896 + c0 + cc];
        }
        __syncthreads();
        const float* src; int cb;
        if (c0 < 128){ src = x3 + (size_t)b*128*N_SP; cb = c0; }
        else if (c0 < 384){ src = g_x2u + (size_t)b*256*N_SP; cb = c0 - 128; }
        else { src = g_x1u + (size_t)b*512*N_SP; cb = c0 - 384; }
        #pragma unroll 4
        for (int cc = 0; cc < 32; cc++){
            float x = src[(size_t)(cb+cc)*N_SP + n];
            ull xx = dup2(x);
            const ulonglong2* wp = (const ulonglong2*)(Ws2 + cc*32);
            #pragma unroll
            for (int j = 0; j < 8; j++){
                ulonglong2 wv = wp[j];
                ffma2(tacc[2*j],   wv.x, xx);
                ffma2(tacc[2*j+1], wv.y, xx);
            }
        }
    }

    float prod = g_a[p] * g_a[HB*N_SP + p] * g_a[2*HB*N_SP + p];
    float res = b2[0];
    #pragma unroll
    for (int j = 0; j < 8; j++){
        float t0, t1, t2, t3;
        unpack2(tacc[2*j],   t0, t1);
        unpack2(tacc[2*j+1], t2, t3);
        int o = 4*j;
        res += w2[o]   * fmaxf(prod*t0 + b1[o],   0.f);
        res += w2[o+1] * fmaxf(prod*t1 + b1[o+1], 0.f);
        res += w2[o+2] * fmaxf(prod*t2 + b1[o+2], 0.f);
        res += w2[o+3] * fmaxf(prod*t3 + b1[o+3], 0.f);
    }
    out[p] = res;
}

// ---------------- host launcher ----------------
extern "C" void kernel_launch(void* const* d_in, const int* in_sizes, int n_in,
                              void* d_out, int out_size)
{
    const float* x3 = (const float*)d_in[0];
    const float* x2 = (const float*)d_in[1];
    const float* x1 = (const float*)d_in[2];

    float *px2u, *px1u, *pq, *pk, *ps, *pa, *pu, *psb;
    cudaGetSymbolAddress((void**)&px2u, g_x2u);
    cudaGetSymbolAddress((void**)&px1u, g_x1u);
    cudaGetSymbolAddress((void**)&pq,   g_q);
    cudaGetSymbolAddress((void**)&pk,   g_k);
    cudaGetSymbolAddress((void**)&ps,   g_s);
    cudaGetSymbolAddress((void**)&pa,   g_a);
    cudaGetSymbolAddress((void**)&pu,   g_u);
    cudaGetSymbolAddress((void**)&psb,  g_sb);

    const int SMEM64 = (2*64*128 + 128 + 8*64*4) * 4;   // 74240
    const int SMEM32 = (2*32*128 + 128 + 8*64*4) * 4;   // 41472
    const int SMEM16 = (2*16*128 + 128 + 8*64*4) * 4;   // 25088
    cudaFuncSetAttribute(attn_kernel<64>, cudaFuncAttributeMaxDynamicSharedMemorySize, SMEM64);

    // 1) upsample x2 -> 64x64 (1024 planes), x1 -> 64x64 (2048 planes)
    upsample_kernel<<<(HB*256*N_SP)/256, 256>>>(x2, px2u, HB*256, 32);
    upsample_kernel<<<(HB*512*N_SP)/256, 256>>>(x1, px1u, HB*512, 16);

    // 2) fold value path: u = wa @ Wv, sb = wa . bv  (scale0=C512 on x1u, scale1=C256, scale2=C128)
    u_kernel<<<2, 256>>>((const float*)d_in[9],  (const float*)d_in[7],  (const float*)d_in[8],  pu,        psb,     512);
    u_kernel<<<1, 256>>>((const float*)d_in[17], (const float*)d_in[15], (const float*)d_in[16], pu + 512,  psb + 1, 256);
    u_kernel<<<1, 256>>>((const float*)d_in[25], (const float*)d_in[23], (const float*)d_in[24], pu + 1024, psb + 2, 128);

    // 3) scalar values s[b,m]
    dim3 sg(16, HB);
    s_kernel<512><<<sg, 256>>>(px1u, pu,        psb,     ps);
    s_kernel<256><<<sg, 256>>>(px2u, pu + 512,  psb + 1, ps + HB*N_SP);
    s_kernel<128><<<sg, 256>>>(x3,   pu + 1024, psb + 2, ps + 2*HB*N_SP);

    // 4) q/k projections (q pre-scaled by log2e)
    dim3 pg(64, HB);
    qkprep_kernel<512,64><<<pg, 256>>>(px1u, (const float*)d_in[3],  (const float*)d_in[4],
                                             (const float*)d_in[5],  (const float*)d_in[6],
                                             pq + Q_OFF0, pk + Q_OFF0);
    qkprep_kernel<256,32><<<pg, 256>>>(px2u, (const float*)d_in[11], (const float*)d_in[12],
                                             (const float*)d_in[13], (const float*)d_in[14],
                                             pq + Q_OFF1, pk + Q_OFF1);
    qkprep_kernel<128,16><<<pg, 256>>>(x3,   (const float*)d_in[19], (const float*)d_in[20],
                                             (const float*)d_in[21], (const float*)d_in[22],
                                             pq + Q_OFF2, pk + Q_OFF2);

    // 5) attention with scalar values -> per-scale attention maps
    dim3 ag(64, HB);
    attn_kernel<64><<<ag, 256, SMEM64>>>(pq + Q_OFF0, pk + Q_OFF0, ps,             (const float*)d_in[10], pa);
    attn_kernel<32><<<ag, 256, SMEM32>>>(pq + Q_OFF1, pk + Q_OFF1, ps + HB*N_SP,   (const float*)d_in[18], pa + HB*N_SP);
    attn_kernel<16><<<ag, 256, SMEM16>>>(pq + Q_OFF2, pk + Q_OFF2, ps + 2*HB*N_SP, (const float*)d_in[26], pa + 2*HB*N_SP);

    // 6) fused final: prod of maps, modulate xcat, conv->relu->conv
    final_kernel<<<(HB*N_SP)/128, 128>>>(x3, (const float*)d_in[27], (const float*)d_in[28],
                                         (const float*)d_in[29], (const float*)d_in[30],
                                         (float*)d_out);
}

// round 10
// speedup vs baseline: 1.0690x; 1.0690x over previous
#include <cuda_runtime.h>
#include <cstdint>
#include <cstddef>

#define N_SP 4096
#define HB 4
#define LOG2E 1.4426950408889634f

typedef unsigned long long ull;

// ---------------- packed f32x2 helpers ----------------
__device__ __forceinline__ void ffma2(ull &d, ull a, ull b){
    asm("fma.rn.f32x2 %0, %1, %2, %0;" : "+l"(d) : "l"(a), "l"(b));
}
__device__ __forceinline__ void unpack2(ull v, float &lo, float &hi){
    asm("mov.b64 {%0, %1}, %2;" : "=f"(lo), "=f"(hi) : "l"(v));
}
__device__ __forceinline__ ull dup2(float x){
    ull r; asm("mov.b64 %0, {%1, %1};" : "=l"(r) : "f"(x)); return r;
}
__device__ __forceinline__ float fexp2(float x){
    float y; asm("ex2.approx.f32 %0, %1;" : "=f"(y) : "f"(x)); return y;
}

// ---------------- scratch (device globals; allocation is forbidden) ----------------
__device__ __align__(128) float g_x2u[HB*256*N_SP];
__device__ __align__(128) float g_x1u[HB*512*N_SP];
__device__ __align__(128) float g_q[HB*(64+32+16)*N_SP];
__device__ __align__(128) float g_k[HB*(64+32+16)*N_SP];
__device__ __align__(128) float g_s[3*HB*N_SP];
__device__ __align__(128) float g_a[3*HB*N_SP];
__device__ __align__(128) float g_u[3*512];
__device__ __align__(128) float g_sb[3];

#define Q_OFF0 0
#define Q_OFF1 (HB*64*N_SP)
#define Q_OFF2 (HB*(64+32)*N_SP)

// ---------------- bilinear upsample (align_corners=True) to 64x64 ----------------
__global__ void upsample_kernel(const float* __restrict__ in, float* __restrict__ out,
                                int planes, int isz)
{
    int idx = blockIdx.x * 256 + threadIdx.x;
    if (idx >= planes * N_SP) return;
    int ox = idx & 63, oy = (idx >> 6) & 63, p = idx >> 12;
    float r = (float)(isz - 1) / 63.0f;
    float cy = oy * r, cx = ox * r;
    int iy = (int)cy; if (iy > isz - 2) iy = isz - 2;
    int ix = (int)cx; if (ix > isz - 2) ix = isz - 2;
    float wy = cy - (float)iy, wx = cx - (float)ix;
    const float* base = in + (size_t)p * isz * isz;
    float v00 = base[iy*isz + ix],     v01 = base[iy*isz + ix + 1];
    float v10 = base[(iy+1)*isz + ix], v11 = base[(iy+1)*isz + ix + 1];
    float top = v00 + wx * (v01 - v00);
    float bot = v10 + wx * (v11 - v10);
    out[idx] = top + wy * (bot - top);
}

// ---------------- u = wa @ Wv (fold value path to 1 channel), sb = wa . bv ----------------
// Parallelized: grid.x = C/64 blocks, 256 threads = 64 c2-cols x 4 c-groups.
template<int C>
__global__ __launch_bounds__(256) void u_kernel(
    const float* __restrict__ wa, const float* __restrict__ Wv,
    const float* __restrict__ bv, float* __restrict__ u, float* __restrict__ sb)
{
    __shared__ float red[4][64];
    int tid = threadIdx.x;
    int c2i = tid & 63;
    int cg  = tid >> 6;                    // 0..3
    int c2  = blockIdx.x * 64 + c2i;
    float acc = 0.f;
    #pragma unroll 8
    for (int c = cg; c < C; c += 4)
        acc += __ldg(&wa[c]) * Wv[c*C + c2];
    red[cg][c2i] = acc;
    __syncthreads();
    if (tid < 64)
        u[blockIdx.x*64 + tid] = red[0][tid] + red[1][tid] + red[2][tid] + red[3][tid];
    if (blockIdx.x == 0 && tid >= 192 && tid < 224){
        int l = tid - 192;
        float a = 0.f;
        for (int c = l; c < C; c += 32) a += wa[c] * bv[c];
        #pragma unroll
        for (int o = 16; o; o >>= 1) a += __shfl_down_sync(0xffffffffu, a, o);
        if (l == 0) *sb = a;
    }
}

// ---------------- s[b,m] = u . x[:,m] + sb ----------------
template<int C>
__global__ void s_kernel(const float* __restrict__ X, const float* __restrict__ u,
                         const float* __restrict__ sb, float* __restrict__ sout)
{
    int b = blockIdx.y;
    int n = blockIdx.x * 256 + threadIdx.x;
    const float* Xb = X + (size_t)b * C * N_SP + n;
    float acc = 0.f;
    #pragma unroll 8
    for (int c = 0; c < C; c++) acc += __ldg(&u[c]) * Xb[(size_t)c * N_SP];
    sout[b*N_SP + n] = acc + sb[0];
}

// ---------------- q/k projection (f32x2 tiled GEMM); q pre-scaled by log2e ----------------
template<int C, int D>
__global__ __launch_bounds__(256) void qkprep_kernel(
    const float* __restrict__ X,
    const float* __restrict__ Wq, const float* __restrict__ bq,
    const float* __restrict__ Wk, const float* __restrict__ bk,
    float* __restrict__ qg, float* __restrict__ kg)
{
    constexpr int ROWS = 2*D;
    constexpr int RP = ROWS/32;            // row-pairs per thread
    __shared__ __align__(16) float Xs2[16*128]; // x duplicated in pairs, [cc][2n]
    __shared__ __align__(16) float Ws[16*ROWS]; // [cc][row]
    int tid = threadIdx.x;
    int cg = tid & 15, rg = tid >> 4;
    int b = blockIdx.y;
    int n0 = blockIdx.x * 64;
    const float* Xb = X + (size_t)b * C * N_SP;

    ull acc[RP][4];
    #pragma unroll
    for (int p = 0; p < RP; p++)
        #pragma unroll
        for (int j = 0; j < 4; j++) acc[p][j] = 0ull;

    for (int c0 = 0; c0 < C; c0 += 16){
        __syncthreads();
        #pragma unroll
        for (int i = 0; i < 4; i++){
            int idx = tid + i*256;
            int cc = idx >> 6, n = idx & 63;
            float v = Xb[(size_t)(c0+cc)*N_SP + n0 + n];
            *(float2*)&Xs2[cc*128 + 2*n] = make_float2(v, v);
        }
        #pragma unroll
        for (int i = 0; i < ROWS/16; i++){
            int idx = tid + i*256;
            int cc = idx & 15, r = idx >> 4;
            Ws[cc*ROWS + r] = (r < D) ? Wq[r*C + c0 + cc] : Wk[(r-D)*C + c0 + cc];
        }
        __syncthreads();
        #pragma unroll
        for (int cc = 0; cc < 16; cc++){
            const ulonglong2* xp = (const ulonglong2*)(Xs2 + cc*128 + cg*8);
            ulonglong2 xa = xp[0], xb2 = xp[1];
            ull x0 = xa.x, x1 = xa.y, x2 = xb2.x, x3 = xb2.y;
            ull wv[RP];
            if constexpr (RP == 4){
                const ulonglong2* wq2 = (const ulonglong2*)&Ws[cc*ROWS + rg*8];
                ulonglong2 wA = wq2[0], wB = wq2[1];
                wv[0] = wA.x; wv[1] = wA.y; wv[2] = wB.x; wv[3] = wB.y;
            } else if constexpr (RP == 2){
                ulonglong2 wA = *(const ulonglong2*)&Ws[cc*ROWS + rg*4];
                wv[0] = wA.x; wv[1] = wA.y;
            } else {
                wv[0] = *(const ull*)&Ws[cc*ROWS + rg*2];
            }
            #pragma unroll
            for (int p = 0; p < RP; p++){
                ffma2(acc[p][0], wv[p], x0);
                ffma2(acc[p][1], wv[p], x1);
                ffma2(acc[p][2], wv[p], x2);
                ffma2(acc[p][3], wv[p], x3);
            }
        }
    }
    #pragma unroll
    for (int p = 0; p < RP; p++){
        int r0 = (rg*RP + p)*2;
        #pragma unroll
        for (int j = 0; j < 4; j++){
            float lo, hi; unpack2(acc[p][j], lo, hi);
            int n = n0 + cg*4 + j;
            if (r0 < D){
                qg[((size_t)b*D + r0)*N_SP + n]     = (lo + bq[r0])   * LOG2E;
                qg[((size_t)b*D + r0 + 1)*N_SP + n] = (hi + bq[r0+1]) * LOG2E;
            } else {
                int rr = r0 - D;
                kg[((size_t)b*D + rr)*N_SP + n]     = lo + bk[rr];
                kg[((size_t)b*D + rr + 1)*N_SP + n] = hi + bk[rr+1];
            }
        }
    }
}

// ---------------- streaming attention with scalar values ----------------
// a[n] = ba + sum_m 2^(l[n,m]-M) s[m] / sum_m 2^(l[n,m]-M),   l = log2e*(q.k)
template<int D>
__global__ __launch_bounds__(256, 2) void attn_kernel(
    const float* __restrict__ qg, const float* __restrict__ kg,
    const float* __restrict__ sg, const float* __restrict__ bap,
    float* __restrict__ aout)
{
    extern __shared__ float sm[];
    float* smq = sm;                  // D*128 floats (q duplicated in pairs)
    float* smk = sm + D*128;          // D*128 floats
    float* sms = smk + D*128;         // 128 floats
    float* smr = sms + 128;           // 8*64*4 floats
    int tid = threadIdx.x;
    int lane = tid & 31, w = tid >> 5;
    int b = blockIdx.y, n0 = blockIdx.x * 64;
    const float* qb = qg + (size_t)b * D * N_SP;
    const float* kb = kg + (size_t)b * D * N_SP;
    const float* sb = sg + (size_t)b * N_SP;

    #pragma unroll
    for (int i = 0; i < (D*64)/256; i++){
        int idx = tid + i*256;
        int kk = idx >> 6, n = idx & 63;
        float v = qb[(size_t)kk*N_SP + n0 + n];
        *(float2*)&smq[kk*128 + 2*n] = make_float2(v, v);
    }

    float mx0 = -1e30f, mx1 = -1e30f;
    float den0 = 0.f, den1 = 0.f, num0 = 0.f, num1 = 0.f;

    for (int mt = 0; mt < 32; mt++){
        __syncthreads();
        #pragma unroll
        for (int i = 0; i < (D*128)/1024; i++){
            int qi = tid + i*256;
            int kk = qi >> 5, mq = qi & 31;
            *(float4*)&smk[kk*128 + mq*4] =
                *(const float4*)&kb[(size_t)kk*N_SP + mt*128 + mq*4];
        }
        if (tid < 32)
            *(float4*)&sms[tid*4] = *(const float4*)&sb[mt*128 + tid*4];
        __syncthreads();

        ull acc[16];
        #pragma unroll
        for (int j = 0; j < 16; j++) acc[j] = 0ull;

        #pragma unroll 8
        for (int kk = 0; kk < D; kk++){
            ulonglong2 qp = ((const ulonglong2*)(smq + kk*128))[lane];
            const ulonglong2* kr = (const ulonglong2*)(smk + kk*128) + w*4;
            ulonglong2 k0 = kr[0], k1 = kr[1], k2 = kr[2], k3 = kr[3];
            ffma2(acc[0],  qp.x, k0.x); ffma2(acc[1],  qp.x, k0.y);
            ffma2(acc[2],  qp.x, k1.x); ffma2(acc[3],  qp.x, k1.y);
            ffma2(acc[4],  qp.x, k2.x); ffma2(acc[5],  qp.x, k2.y);
            ffma2(acc[6],  qp.x, k3.x); ffma2(acc[7],  qp.x, k3.y);
            ffma2(acc[8],  qp.y, k0.x); ffma2(acc[9],  qp.y, k0.y);
            ffma2(acc[10], qp.y, k1.x); ffma2(acc[11], qp.y, k1.y);
            ffma2(acc[12], qp.y, k2.x); ffma2(acc[13], qp.y, k2.y);
            ffma2(acc[14], qp.y, k3.x); ffma2(acc[15], qp.y, k3.y);
        }

        float sv[16];
        #pragma unroll
        for (int j = 0; j < 4; j++)
            *(float4*)&sv[4*j] = *(const float4*)&sms[w*16 + 4*j];

        {   // row 0 (n = n0 + 2*lane)
            float l[16];
            #pragma unroll
            for (int j = 0; j < 8; j++) unpack2(acc[j], l[2*j], l[2*j+1]);
            float tm = mx0;
            #pragma unroll
            for (int j = 0; j < 16; j++) tm = fmaxf(tm, l[j]);
            float sc = fexp2(mx0 - tm);
            den0 *= sc; num0 *= sc; mx0 = tm;
            float dl = 0.f, nl = 0.f;
            #pragma unroll
            for (int j = 0; j < 16; j++){
                float e = fexp2(l[j] - tm);
                dl += e; nl += e * sv[j];
            }
            den0 += dl; num0 += nl;
        }
        {   // row 1 (n = n0 + 2*lane + 1)
            float l[16];
            #pragma unroll
            for (int j = 0; j < 8; j++) unpack2(acc[8+j], l[2*j], l[2*j+1]);
            float tm = mx1;
            #pragma unroll
            for (int j = 0; j < 16; j++) tm = fmaxf(tm, l[j]);
            float sc = fexp2(mx1 - tm);
            den1 *= sc; num1 *= sc; mx1 = tm;
            float dl = 0.f, nl = 0.f;
            #pragma unroll
            for (int j = 0; j < 16; j++){
                float e = fexp2(l[j] - tm);
                dl += e; nl += e * sv[j];
            }
            den1 += dl; num1 += nl;
        }
    }

    // per-warp partials -> smem, reduce across the 8 warps
    {
        int r0 = lane*2;
        float* p0 = &smr[(w*64 + r0)*4];
        p0[0] = mx0; p0[1] = den0; p0[2] = num0;
        float* p1 = &smr[(w*64 + r0 + 1)*4];
        p1[0] = mx1; p1[1] = den1; p1[2] = num1;
    }
    __syncthreads();
    if (tid < 64){
        float M = -1e30f;
        #pragma unroll
        for (int i = 0; i < 8; i++) M = fmaxf(M, smr[(i*64 + tid)*4]);
        float dsum = 0.f, nsum = 0.f;
        #pragma unroll
        for (int i = 0; i < 8; i++){
            float e = fexp2(smr[(i*64 + tid)*4] - M);
            dsum += smr[(i*64 + tid)*4 + 1] * e;
            nsum += smr[(i*64 + tid)*4 + 2] * e;
        }
        aout[(size_t)b*N_SP + n0 + tid] = bap[0] + nsum / dsum;
    }
}

// ---------------- final fused conv: out = w2 . relu(prod * (W1 . xcat) + b1) + b2 ----------------
__global__ __launch_bounds__(128) void final_kernel(
    const float* __restrict__ x3, const float* __restrict__ w1,
    const float* __restrict__ b1, const float* __restrict__ w2,
    const float* __restrict__ b2, float* __restrict__ out)
{
    __shared__ __align__(16) float Ws2[32*32];
    int tid = threadIdx.x;
    int p = blockIdx.x * 128 + tid;
    int b = p >> 12, n = p & 4095;

    ull tacc[16];
    #pragma unroll
    for (int j = 0; j < 16; j++) tacc[j] = 0ull;

    for (int c0 = 0; c0 < 896; c0 += 32){
        __syncthreads();
        #pragma unroll
        for (int i = 0; i < 8; i++){
            int idx = tid + i*128;
            int o = idx >> 5, cc = idx & 31;
            Ws2[cc*32 + o] = w1[o*896 + c0 + cc];
        }
        __syncthreads();
        const float* src; int cb;
        if (c0 < 128){ src = x3 + (size_t)b*128*N_SP; cb = c0; }
        else if (c0 < 384){ src = g_x2u + (size_t)b*256*N_SP; cb = c0 - 128; }
        else { src = g_x1u + (size_t)b*512*N_SP; cb = c0 - 384; }
        #pragma unroll 4
        for (int cc = 0; cc < 32; cc++){
            float x = src[(size_t)(cb+cc)*N_SP + n];
            ull xx = dup2(x);
            const ulonglong2* wp = (const ulonglong2*)(Ws2 + cc*32);
            #pragma unroll
            for (int j = 0; j < 8; j++){
                ulonglong2 wv = wp[j];
                ffma2(tacc[2*j],   wv.x, xx);
                ffma2(tacc[2*j+1], wv.y, xx);
            }
        }
    }

    float prod = g_a[p] * g_a[HB*N_SP + p] * g_a[2*HB*N_SP + p];
    float res = b2[0];
    #pragma unroll
    for (int j = 0; j < 8; j++){
        float t0, t1, t2, t3;
        unpack2(tacc[2*j],   t0, t1);
        unpack2(tacc[2*j+1], t2, t3);
        int o = 4*j;
        res += w2[o]   * fmaxf(prod*t0 + b1[o],   0.f);
        res += w2[o+1] * fmaxf(prod*t1 + b1[o+1], 0.f);
        res += w2[o+2] * fmaxf(prod*t2 + b1[o+2], 0.f);
        res += w2[o+3] * fmaxf(prod*t3 + b1[o+3], 0.f);
    }
    out[p] = res;
}

// ---------------- host launcher ----------------
// Launch order is chosen so that launch #6 (ncu capture window: -s 5 -c 1)
// is attn_kernel<64>, the dominant kernel.
extern "C" void kernel_launch(void* const* d_in, const int* in_sizes, int n_in,
                              void* d_out, int out_size)
{
    const float* x3 = (const float*)d_in[0];
    const float* x2 = (const float*)d_in[1];
    const float* x1 = (const float*)d_in[2];

    float *px2u, *px1u, *pq, *pk, *ps, *pa, *pu, *psb;
    cudaGetSymbolAddress((void**)&px2u, g_x2u);
    cudaGetSymbolAddress((void**)&px1u, g_x1u);
    cudaGetSymbolAddress((void**)&pq,   g_q);
    cudaGetSymbolAddress((void**)&pk,   g_k);
    cudaGetSymbolAddress((void**)&ps,   g_s);
    cudaGetSymbolAddress((void**)&pa,   g_a);
    cudaGetSymbolAddress((void**)&pu,   g_u);
    cudaGetSymbolAddress((void**)&psb,  g_sb);

    const int SMEM64 = (2*64*128 + 128 + 8*64*4) * 4;   // 74240
    const int SMEM32 = (2*32*128 + 128 + 8*64*4) * 4;   // 41472
    const int SMEM16 = (2*16*128 + 128 + 8*64*4) * 4;   // 25088
    cudaFuncSetAttribute(attn_kernel<64>, cudaFuncAttributeMaxDynamicSharedMemorySize, SMEM64);

    dim3 sg(16, HB);
    dim3 pg(64, HB);
    dim3 ag(64, HB);

    // --- scale 0 chain (C=512, D=64) first, so attn<64> is launch #6 ---
    // #1: u for scale0 (depends only on weights)
    u_kernel<512><<<8, 256>>>((const float*)d_in[9], (const float*)d_in[7], (const float*)d_in[8], pu, psb);
    // #2: upsample x1 -> x1u
    upsample_kernel<<<(HB*512*N_SP)/256, 256>>>(x1, px1u, HB*512, 16);
    // #3: s for scale0
    s_kernel<512><<<sg, 256>>>(px1u, pu, psb, ps);
    // #4: q/k for scale0
    qkprep_kernel<512,64><<<pg, 256>>>(px1u, (const float*)d_in[3], (const float*)d_in[4],
                                             (const float*)d_in[5], (const float*)d_in[6],
                                             pq + Q_OFF0, pk + Q_OFF0);
    // #5: upsample x2 -> x2u (independent; placed here so #6 is attn<64>)
    upsample_kernel<<<(HB*256*N_SP)/256, 256>>>(x2, px2u, HB*256, 32);
    // #6: attention scale0  <-- ncu capture target
    attn_kernel<64><<<ag, 256, SMEM64>>>(pq + Q_OFF0, pk + Q_OFF0, ps, (const float*)d_in[10], pa);

    // --- scale 1 chain (C=256, D=32) ---
    u_kernel<256><<<4, 256>>>((const float*)d_in[17], (const float*)d_in[15], (const float*)d_in[16], pu + 512, psb + 1);
    s_kernel<256><<<sg, 256>>>(px2u, pu + 512, psb + 1, ps + HB*N_SP);
    qkprep_kernel<256,32><<<pg, 256>>>(px2u, (const float*)d_in[11], (const float*)d_in[12],
                                             (const float*)d_in[13], (const float*)d_in[14],
                                             pq + Q_OFF1, pk + Q_OFF1);
    attn_kernel<32><<<ag, 256, SMEM32>>>(pq + Q_OFF1, pk + Q_OFF1, ps + HB*N_SP, (const float*)d_in[18], pa + HB*N_SP);

    // --- scale 2 chain (C=128, D=16) ---
    u_kernel<128><<<2, 256>>>((const float*)d_in[25], (const float*)d_in[23], (const float*)d_in[24], pu + 1024, psb + 2);
    s_kernel<128><<<sg, 256>>>(x3, pu + 1024, psb + 2, ps + 2*HB*N_SP);
    qkprep_kernel<128,16><<<pg, 256>>>(x3, (const float*)d_in[19], (const float*)d_in[20],
                                            (const float*)d_in[21], (const float*)d_in[22],
                                            pq + Q_OFF2, pk + Q_OFF2);
    attn_kernel<16><<<ag, 256, SMEM16>>>(pq + Q_OFF2, pk + Q_OFF2, ps + 2*HB*N_SP, (const float*)d_in[26], pa + 2*HB*N_SP);

    // --- fused final ---
    final_kernel<<<(HB*N_SP)/128, 128>>>(x3, (const float*)d_in[27], (const float*)d_in[28],
                                         (const float*)d_in[29], (const float*)d_in[30],
                                         (float*)d_out);
}